// round 12
// baseline (speedup 1.0000x reference)
#include <cuda_runtime.h>
#include <cuda_bf16.h>

// Fixed problem constants
#define PH 7
#define PW 7
#define C_CH 256
#define H_FEAT 200
#define W_FEAT 272
#define HW (H_FEAT*W_FEAT)
#define SCALE 0.25f

#define CH_PER_BLOCK 32
#define CHUNKS (C_CH / CH_PER_BLOCK)   // 8
#define NTHREADS 224                   // 7 warps = 7 bin rows
#define CB 8                           // channels batched per inner iteration (4 pairs)

__global__ __launch_bounds__(NTHREADS, 6) void roi_align_occ6(
    const float* __restrict__ feat,
    const float* __restrict__ rois,
    float* __restrict__ out,
    int n_rois)
{
    // Consecutive blocks share a channel chunk -> waves reuse one ~14MB slice in L2.
    const int roi   = blockIdx.x % n_rois;
    const int chunk = blockIdx.x / n_rois;
    const int c0    = chunk * CH_PER_BLOCK;

    const int t    = threadIdx.x;
    const int wid  = t >> 5;            // bin row 0..6
    const int lane = t & 31;
    const int sx   = lane & 15;         // sample col (14,15 idle -> clamped)
    const int sxe  = min(sx, 13);       // idle lanes alias lane 13's sectors (free)
    const bool hi16 = (lane & 16) != 0; // x-high corner half

    // ---- per-ROI setup ----
    const float* r = rois + roi * 5;
    const int   b   = (int)r[0];
    const float swc = r[1] * SCALE;
    const float shc = r[2] * SCALE;
    const float ewc = r[3] * SCALE;
    const float ehc = r[4] * SCALE;
    const float bin_w = fmaxf(ewc - swc, 1.0f) / PW;
    const float bin_h = fmaxf(ehc - shc, 1.0f) / PH;

    // x sample; lanes<16 carry x-low corner, lanes>=16 x-high.
    float x  = swc + ((float)sxe + 0.5f) * 0.5f * bin_w;
    float vx = (x > -1.0f && x < (float)W_FEAT) ? 1.0f : 0.0f;
    float xc = fminf(fmaxf(x, 0.0f), (float)(W_FEAT - 1));
    int   xl = (int)floorf(xc);
    int   xh = min(xl + 1, W_FEAT - 1);
    float lx = xc - (float)xl;
    const int   xcol = hi16 ? xh : xl;
    // 0.25 sample-average prefolded into wx
    float wx = (hi16 ? lx : (1.0f - lx)) * vx * 0.25f;
    if (sx >= 14) wx = 0.0f;            // idle lanes contribute 0

    // two sample rows of this bin row (uniform across warp)
    const int sy0 = wid * 2;
    float y0  = shc + ((float)sy0 + 0.5f) * 0.5f * bin_h;
    float vy0 = (y0 > -1.0f && y0 < (float)H_FEAT) ? 1.0f : 0.0f;
    float yc0 = fminf(fmaxf(y0, 0.0f), (float)(H_FEAT - 1));
    int   yl0 = (int)floorf(yc0);
    float ly0 = yc0 - (float)yl0;
    const int ol0 = yl0 * W_FEAT;
    const int oh0 = min(yl0 + 1, H_FEAT - 1) * W_FEAT;
    const float wly0 = ly0 * vy0;
    const float why0 = (1.0f - ly0) * vy0;

    float y1  = shc + ((float)(sy0 + 1) + 0.5f) * 0.5f * bin_h;
    float vy1 = (y1 > -1.0f && y1 < (float)H_FEAT) ? 1.0f : 0.0f;
    float yc1 = fminf(fmaxf(y1, 0.0f), (float)(H_FEAT - 1));
    int   yl1 = (int)floorf(yc1);
    float ly1 = yc1 - (float)yl1;
    const int ol1 = yl1 * W_FEAT;
    const int oh1 = min(yl1 + 1, H_FEAT - 1) * W_FEAT;
    const float wly1 = ly1 * vy1;
    const float why1 = (1.0f - ly1) * vy1;

    // Four row-base pointers; inner-loop offsets (cc+k)*HW are compile-time
    // immediates (< 8MB), so no per-iteration address IMADs are needed.
    const float* fbase = feat + (b * C_CH + c0) * HW + xcol;
    const float* p00 = fbase + ol0;
    const float* p01 = fbase + oh0;
    const float* p10 = fbase + ol1;
    const float* p11 = fbase + oh1;

    // Writers: even lanes of each half; low half writes pair-channel A, high half B.
    const bool writer = ((lane & 1) == 0) && ((lane & 15) < 14);
    const int obase = (roi * C_CH + c0 + (lane >> 4)) * (PH * PW)
                    + wid * PW + ((lane & 15) >> 1);

    #pragma unroll
    for (int cc = 0; cc < CH_PER_BLOCK; cc += CB) {
        float a0[CB], b0[CB], a1[CB], b1[CB];
        // Batched branch-free loads (compile-time immediate offsets)
        #pragma unroll
        for (int k = 0; k < CB; k++) {
            a0[k] = __ldg(p00 + (cc + k) * HW);   // row yl(sy0)
            b0[k] = __ldg(p01 + (cc + k) * HW);   // row yh(sy0)
            a1[k] = __ldg(p10 + (cc + k) * HW);   // row yl(sy1)
            b1[k] = __ldg(p11 + (cc + k) * HW);   // row yh(sy1)
        }
        // Channel pairs: one shfl per fold serves both channels.
        #pragma unroll
        for (int k = 0; k < CB; k += 2) {
            float sA = why0 * a0[k]   + wly0 * b0[k]   + why1 * a1[k]   + wly1 * b1[k];
            float sB = why0 * a0[k+1] + wly0 * b0[k+1] + why1 * a1[k+1] + wly1 * b1[k+1];
            float vA = wx * sA;
            float vB = wx * sB;
            // corner fold (x-low + x-high), channel-swapped across half-warps
            float sel = hi16 ? vA : vB;
            float tt  = __shfl_xor_sync(0xffffffffu, sel, 16);
            float v2  = (hi16 ? vB : vA) + tt;
            // bin's x-sample pair fold
            float uu  = __shfl_xor_sync(0xffffffffu, v2, 1);
            float v3  = v2 + uu;
            if (writer) out[obase + (cc + k) * (PH * PW)] = v3;
        }
    }
}

extern "C" void kernel_launch(void* const* d_in, const int* in_sizes, int n_in,
                              void* d_out, int out_size) {
    const float* feat = (const float*)d_in[0];
    const float* rois = (const float*)d_in[1];
    float* out = (float*)d_out;

    int n_rois = in_sizes[1] / 5;
    int blocks = n_rois * CHUNKS;
    roi_align_occ6<<<blocks, NTHREADS>>>(feat, rois, out, n_rois);
}

// round 13
// speedup vs baseline: 1.0660x; 1.0660x over previous
#include <cuda_runtime.h>
#include <cuda_bf16.h>

// Fixed problem constants
#define PH 7
#define PW 7
#define C_CH 256
#define H_FEAT 200
#define W_FEAT 272
#define HW (H_FEAT*W_FEAT)
#define SCALE 0.25f

#define CH_PER_BLOCK 64
#define CHUNKS (C_CH / CH_PER_BLOCK)   // 4
#define NTHREADS 224                   // 7 warps = 7 bin rows
#define CB 8                           // channels batched per inner iteration (4 pairs)

__global__ __launch_bounds__(NTHREADS, 5) void roi_align_c64(
    const float* __restrict__ feat,
    const float* __restrict__ rois,
    float* __restrict__ out,
    int n_rois)
{
    // Consecutive blocks share a channel chunk -> a resident wave works on one
    // chunk's ~28MB slice; reuse across overlapping rois happens in L2.
    const int roi   = blockIdx.x % n_rois;
    const int chunk = blockIdx.x / n_rois;
    const int c0    = chunk * CH_PER_BLOCK;

    const int t    = threadIdx.x;
    const int wid  = t >> 5;            // bin row 0..6
    const int lane = t & 31;
    const int sx   = lane & 15;         // sample col (14,15 idle -> clamped)
    const int sxe  = min(sx, 13);       // idle lanes alias lane 13's sectors (free)
    const bool hi16 = (lane & 16) != 0; // x-high corner half

    // ---- per-ROI setup ----
    const float* r = rois + roi * 5;
    const int   b   = (int)r[0];
    const float swc = r[1] * SCALE;
    const float shc = r[2] * SCALE;
    const float ewc = r[3] * SCALE;
    const float ehc = r[4] * SCALE;
    const float bin_w = fmaxf(ewc - swc, 1.0f) / PW;
    const float bin_h = fmaxf(ehc - shc, 1.0f) / PH;

    // x sample; lanes<16 carry x-low corner, lanes>=16 x-high.
    float x  = swc + ((float)sxe + 0.5f) * 0.5f * bin_w;
    float vx = (x > -1.0f && x < (float)W_FEAT) ? 1.0f : 0.0f;
    float xc = fminf(fmaxf(x, 0.0f), (float)(W_FEAT - 1));
    int   xl = (int)floorf(xc);
    int   xh = min(xl + 1, W_FEAT - 1);
    float lx = xc - (float)xl;
    const int   xcol = hi16 ? xh : xl;
    // 0.25 sample-average prefolded into wx
    float wx = (hi16 ? lx : (1.0f - lx)) * vx * 0.25f;
    if (sx >= 14) wx = 0.0f;            // idle lanes contribute 0

    // two sample rows of this bin row (uniform across warp)
    const int sy0 = wid * 2;
    float y0  = shc + ((float)sy0 + 0.5f) * 0.5f * bin_h;
    float vy0 = (y0 > -1.0f && y0 < (float)H_FEAT) ? 1.0f : 0.0f;
    float yc0 = fminf(fmaxf(y0, 0.0f), (float)(H_FEAT - 1));
    int   yl0 = (int)floorf(yc0);
    float ly0 = yc0 - (float)yl0;
    const int ol0 = yl0 * W_FEAT;
    const int oh0 = min(yl0 + 1, H_FEAT - 1) * W_FEAT;
    const float wly0 = ly0 * vy0;
    const float why0 = (1.0f - ly0) * vy0;

    float y1  = shc + ((float)(sy0 + 1) + 0.5f) * 0.5f * bin_h;
    float vy1 = (y1 > -1.0f && y1 < (float)H_FEAT) ? 1.0f : 0.0f;
    float yc1 = fminf(fmaxf(y1, 0.0f), (float)(H_FEAT - 1));
    int   yl1 = (int)floorf(yc1);
    float ly1 = yc1 - (float)yl1;
    const int ol1 = yl1 * W_FEAT;
    const int oh1 = min(yl1 + 1, H_FEAT - 1) * W_FEAT;
    const float wly1 = ly1 * vy1;
    const float why1 = (1.0f - ly1) * vy1;

    // Four row-base pointers; inner-loop offsets (cc+k)*HW are compile-time
    // immediates, so no per-iteration address IMADs are needed.
    const float* fbase = feat + (b * C_CH + c0) * HW + xcol;
    const float* p00 = fbase + ol0;
    const float* p01 = fbase + oh0;
    const float* p10 = fbase + ol1;
    const float* p11 = fbase + oh1;

    // Writers: even lanes of each half; low half writes pair-channel A, high half B.
    const bool writer = ((lane & 1) == 0) && ((lane & 15) < 14);
    const int obase = (roi * C_CH + c0 + (lane >> 4)) * (PH * PW)
                    + wid * PW + ((lane & 15) >> 1);

    #pragma unroll
    for (int cc = 0; cc < CH_PER_BLOCK; cc += CB) {
        float a0[CB], b0[CB], a1[CB], b1[CB];
        // Batched branch-free loads: 4*CB = 32 outstanding LDGs per warp
        #pragma unroll
        for (int k = 0; k < CB; k++) {
            a0[k] = __ldg(p00 + (cc + k) * HW);   // row yl(sy0)
            b0[k] = __ldg(p01 + (cc + k) * HW);   // row yh(sy0)
            a1[k] = __ldg(p10 + (cc + k) * HW);   // row yl(sy1)
            b1[k] = __ldg(p11 + (cc + k) * HW);   // row yh(sy1)
        }
        // Channel pairs: one shfl per fold serves both channels.
        #pragma unroll
        for (int k = 0; k < CB; k += 2) {
            float sA = why0 * a0[k]   + wly0 * b0[k]   + why1 * a1[k]   + wly1 * b1[k];
            float sB = why0 * a0[k+1] + wly0 * b0[k+1] + why1 * a1[k+1] + wly1 * b1[k+1];
            float vA = wx * sA;
            float vB = wx * sB;
            // corner fold (x-low + x-high), channel-swapped across half-warps
            float sel = hi16 ? vA : vB;
            float tt  = __shfl_xor_sync(0xffffffffu, sel, 16);
            float v2  = (hi16 ? vB : vA) + tt;
            // bin's x-sample pair fold
            float uu  = __shfl_xor_sync(0xffffffffu, v2, 1);
            float v3  = v2 + uu;
            if (writer) out[obase + (cc + k) * (PH * PW)] = v3;
        }
    }
}

extern "C" void kernel_launch(void* const* d_in, const int* in_sizes, int n_in,
                              void* d_out, int out_size) {
    const float* feat = (const float*)d_in[0];
    const float* rois = (const float*)d_in[1];
    float* out = (float*)d_out;

    int n_rois = in_sizes[1] / 5;
    int blocks = n_rois * CHUNKS;
    roi_align_c64<<<blocks, NTHREADS>>>(feat, rois, out, n_rois);
}